// round 13
// baseline (speedup 1.0000x reference)
#include <cuda_runtime.h>
#include <cuda_fp16.h>
#include <cstdint>

// ---------------- problem constants ----------------
static constexpr int Bb = 4, Ss = 8192, Ff = 1024, Hh = 16, Dd = 64;
static constexpr int Mm = Bb * Ss;              // 32768
static constexpr int Kk = 1024, Nn = 1024;
static constexpr long QELEMS = (long)Mm * Ff;   // 33554432
static constexpr int NCHUNK = 32;
static constexpr int ROWS_PER_CHUNK = 8192 / NCHUNK;  // 256

// ---------------- scratch (device globals) ----------------
__device__ __half gQh[33554432];                // Q projection, fp16
__device__ __half gKh[33554432];                // K projection, fp16
__device__ __half gVh[33554432];                // V projection, fp16
__device__ float gPpart[(long)NCHUNK * 64 * 4096];
__device__ __half gPh[64 * 4096];               // fp16 copy of p_attn for out HMMA
__device__ __half gAh[3L * 33554432];
__device__ __half gWt[3L * 1048576];            // W^T: [n][k], k contiguous, fp16

// ---------------- helpers ----------------
__device__ __forceinline__ uint32_t smem_u32(const void* p) {
    uint32_t a;
    asm("{ .reg .u64 t; cvta.to.shared.u64 t, %1; cvt.u32.u64 %0, t; }" : "=r"(a) : "l"(p));
    return a;
}
// Swizzle<3,4,3> for 128B rows: XOR 16B-chunk bits [4:6] with row bits [7:9]
__device__ __forceinline__ uint32_t SZ128(uint32_t a) { return a ^ ((a >> 3) & 0x70u); }

__device__ __forceinline__ void cp16(uint32_t dst, const void* src) {
    asm volatile("cp.async.cg.shared.global [%0], [%1], 16;\n" :: "r"(dst), "l"(src));
}
__device__ __forceinline__ void cp_commit() { asm volatile("cp.async.commit_group;\n"); }
template<int N> __device__ __forceinline__ void cp_wait() {
    asm volatile("cp.async.wait_group %0;\n" :: "n"(N));
}
__device__ __forceinline__ void ldm4(uint32_t* r, uint32_t addr) {
    asm volatile("ldmatrix.sync.aligned.m8n8.x4.shared.b16 {%0,%1,%2,%3}, [%4];"
                 : "=r"(r[0]), "=r"(r[1]), "=r"(r[2]), "=r"(r[3]) : "r"(addr));
}
__device__ __forceinline__ void ldm4t(uint32_t* r, uint32_t addr) {
    asm volatile("ldmatrix.sync.aligned.m8n8.x4.trans.shared.b16 {%0,%1,%2,%3}, [%4];"
                 : "=r"(r[0]), "=r"(r[1]), "=r"(r[2]), "=r"(r[3]) : "r"(addr));
}
__device__ __forceinline__ void mma16816(float* d, const uint32_t* a, const uint32_t* b) {
    asm volatile(
        "mma.sync.aligned.m16n8k16.row.col.f32.f16.f16.f32 "
        "{%0,%1,%2,%3}, {%4,%5,%6,%7}, {%8,%9}, {%0,%1,%2,%3};"
        : "+f"(d[0]), "+f"(d[1]), "+f"(d[2]), "+f"(d[3])
        : "r"(a[0]), "r"(a[1]), "r"(a[2]), "r"(a[3]), "r"(b[0]), "r"(b[1]));
}

// ---------------- conversion prepasses ----------------
__global__ __launch_bounds__(256)
void convert_A_kernel(const float* __restrict__ q, const float* __restrict__ k,
                      const float* __restrict__ v)
{
    const int which = blockIdx.y;
    const float* src = (which == 0) ? q : (which == 1) ? k : v;
    __half* hi = gAh + (size_t)which * 33554432;

    size_t i8 = (size_t)blockIdx.x * blockDim.x + threadIdx.x;   // 0..4194303
    float4 x0 = reinterpret_cast<const float4*>(src)[2 * i8];
    float4 x1 = reinterpret_cast<const float4*>(src)[2 * i8 + 1];

    __half2 a0 = __halves2half2(__float2half_rn(x0.x), __float2half_rn(x0.y));
    __half2 a1 = __halves2half2(__float2half_rn(x0.z), __float2half_rn(x0.w));
    __half2 a2 = __halves2half2(__float2half_rn(x1.x), __float2half_rn(x1.y));
    __half2 a3 = __halves2half2(__float2half_rn(x1.z), __float2half_rn(x1.w));
    uint4 u;
    u.x = *reinterpret_cast<unsigned*>(&a0);
    u.y = *reinterpret_cast<unsigned*>(&a1);
    u.z = *reinterpret_cast<unsigned*>(&a2);
    u.w = *reinterpret_cast<unsigned*>(&a3);
    reinterpret_cast<uint4*>(hi)[i8] = u;
}

__global__ __launch_bounds__(256)
void convert_W_kernel(const float* __restrict__ wq, const float* __restrict__ wk,
                      const float* __restrict__ wv)
{
    const int which = blockIdx.z;
    const float* W = (which == 0) ? wq : (which == 1) ? wk : wv;
    __half* hi = gWt + (size_t)which * 1048576;

    __shared__ float tile[32][33];
    const int bx = blockIdx.x * 32;   // n block
    const int by = blockIdx.y * 32;   // k block
    const int tx = threadIdx.x & 31;
    const int ty = threadIdx.x >> 5;  // 0..7

#pragma unroll
    for (int i = 0; i < 32; i += 8)
        tile[ty + i][tx] = W[(size_t)(by + ty + i) * 1024 + bx + tx];
    __syncthreads();
#pragma unroll
    for (int i = 0; i < 32; i += 8) {
        float x = tile[tx][ty + i];                 // = W[by+tx][bx+ty+i]
        size_t o = (size_t)(bx + ty + i) * 1024 + by + tx;   // Wt[n][k]
        hi[o] = __float2half_rn(x);
    }
}

// ---------------- HMMA GEMM: C[M,N] = A @ W  (fp16, 3-stage, occ 2) ----------
// Tile 128x128xK64, 8 warps (2m x 4n, 64x32 warp tiles), 3-stage cp.async.
static constexpr int STAGE = 32768;
static constexpr int NCH = 16;        // 1024 / 64

__global__ __launch_bounds__(256, 2)
void gemm_mma_kernel()
{
    extern __shared__ char smem[];
    const int which = blockIdx.z;
    const int n0 = blockIdx.x * 128;
    const int m0 = blockIdx.y * 128;
    const int tid = threadIdx.x;
    const int wid = tid >> 5, lane = tid & 31;

    const uint32_t tiles = (smem_u32(smem) + 1023) & ~1023u;

    const __half* Ah = gAh + (size_t)which * 33554432;
    const __half* Bp = gWt + (size_t)which * 1048576;

    const int mbase_w = (wid & 1) * 64;
    const int nbase_w = (wid >> 1) * 32;

    float acc[4][4][4];
#pragma unroll
    for (int i = 0; i < 4; i++)
#pragma unroll
        for (int j = 0; j < 4; j++)
#pragma unroll
            for (int q = 0; q < 4; q++) acc[i][j][q] = 0.f;

    auto load_chunk = [&](int buf, int c) {
        const uint32_t base = tiles + buf * STAGE;
        const int k0 = c * 64;
#pragma unroll
        for (int i = tid; i < 1024; i += 256) {         // A: 128 rows x 8 chunks
            int r = i >> 3, c8 = i & 7;
            size_t gb = ((size_t)(m0 + r) * 1024 + k0 + c8 * 8) * 2;
            uint32_t d = SZ128((uint32_t)(r * 128 + c8 * 16));
            cp16(base + d, (const char*)Ah + gb);
        }
#pragma unroll
        for (int i = tid; i < 1024; i += 256) {         // B: 128 rows x 8 chunks
            int r = i >> 3, c8 = i & 7;
            size_t gb = ((size_t)(n0 + r) * 1024 + k0 + c8 * 8) * 2;
            uint32_t d = SZ128((uint32_t)(r * 128 + c8 * 16));
            cp16(base + 16384 + d, (const char*)Bp + gb);
        }
        cp_commit();
    };

    load_chunk(0, 0);
    load_chunk(1, 1);

    const int arow = (lane & 7) + ((lane >> 3) & 1) * 8;
    const int aoff = ((lane >> 4) & 1) * 16;
    const int brow = (lane & 7) + ((lane >> 4) & 1) * 8;
    const int boff = ((lane >> 3) & 1) * 16;

    int buf = 0;
    for (int c = 0; c < NCH; ++c) {
        if (c < NCH - 1) cp_wait<1>(); else cp_wait<0>();
        __syncthreads();
        if (c + 2 < NCH) load_chunk((buf + 2) % 3, c + 2);

        const uint32_t ab = tiles + buf * STAGE;
        const uint32_t bb = ab + 16384;

#pragma unroll
        for (int s = 0; s < 4; ++s) {
            uint32_t ah[4][4], bh2[4][2];
#pragma unroll
            for (int bg = 0; bg < 2; ++bg) {
                uint32_t u = SZ128((uint32_t)((nbase_w + bg * 16 + brow) * 128 + s * 32 + boff));
                uint32_t r[4];
                ldm4(r, bb + u);
                bh2[2 * bg][0] = r[0]; bh2[2 * bg][1] = r[1];
                bh2[2 * bg + 1][0] = r[2]; bh2[2 * bg + 1][1] = r[3];
            }
#pragma unroll
            for (int mf = 0; mf < 4; ++mf) {
                uint32_t u = SZ128((uint32_t)((mbase_w + mf * 16 + arow) * 128 + s * 32 + aoff));
                ldm4(ah[mf], ab + u);
            }
#pragma unroll
            for (int mf = 0; mf < 4; ++mf)
#pragma unroll
                for (int nf = 0; nf < 4; ++nf)
                    mma16816(acc[mf][nf], ah[mf], bh2[nf]);
        }
        buf = (buf + 1) % 3;
    }

    // epilogue: all projections stored fp16
    __half* Ch = (which == 0) ? gQh : (which == 1) ? gKh : gVh;
    const int lrow = lane >> 2;
    const int lcol = (lane & 3) * 2;
#pragma unroll
    for (int mf = 0; mf < 4; ++mf)
#pragma unroll
        for (int nf = 0; nf < 4; ++nf) {
            int rm = m0 + mbase_w + mf * 16 + lrow;
            int cn = n0 + nbase_w + nf * 8 + lcol;
            *reinterpret_cast<__half2*>(Ch + (size_t)rm * 1024 + cn) =
                __floats2half2_rn(acc[mf][nf][0], acc[mf][nf][1]);
            *reinterpret_cast<__half2*>(Ch + (size_t)(rm + 8) * 1024 + cn) =
                __floats2half2_rn(acc[mf][nf][2], acc[mf][nf][3]);
        }
}

// ---------------- p_attn partials: LN(K)^T LN(V), HMMA consumer --------------
// 32 rows staged per iteration (4 rows/warp), 2 MMA k-steps per sync.
// Accumulation order over 16-row groups identical to the 16-row version.
__global__ __launch_bounds__(256)
void pattn_partial_kernel(const float* __restrict__ lnk_s, const float* __restrict__ lnk_b,
                          const float* __restrict__ lnv_s, const float* __restrict__ lnv_b)
{
    const int bh = blockIdx.x;
    const int chunk = blockIdx.y;
    const int b = bh >> 4, h = bh & 15;
    const int n0 = chunk * ROWS_PER_CHUNK;
    const long base = (long)b * (Ss * Ff) + (long)h * (512 * 1024);

    __shared__ __half ksh[32][72];
    __shared__ __half vsh[32][72];
    __shared__ float sks[64], skb[64], svs[64], svb[64];

    const int t = threadIdx.x;
    const int warp = t >> 5, lane = t & 31;

    if (t < 64) {
        sks[t] = lnk_s[h * 64 + t];
        skb[t] = lnk_b[h * 64 + t];
        svs[t] = lnv_s[h * 64 + t];
        svb[t] = lnv_b[h * 64 + t];
    }

    const int d0 = (warp >> 1) * 16;
    const int e0 = (warp & 1) * 32;

    const uint32_t aaddr = smem_u32(
        &ksh[(lane & 7) + ((lane >> 4) & 1) * 8][d0 + ((lane >> 3) & 1) * 8]);
    const uint32_t baddr0 = smem_u32(
        &vsh[(lane & 7) + ((lane >> 3) & 1) * 8][e0 + ((lane >> 4) & 1) * 8]);
    const uint32_t baddr1 = baddr0 + 16 * 2;
    const uint32_t rowstep = 16 * 72 * 2;   // 16 smem rows in bytes

    float acc[4][4];
#pragma unroll
    for (int i = 0; i < 4; i++)
#pragma unroll
        for (int j = 0; j < 4; j++) acc[i][j] = 0.f;

    for (int r0 = 0; r0 < ROWS_PER_CHUNK; r0 += 32) {
        __syncthreads();
#pragma unroll
        for (int rr = 0; rr < 4; rr++) {
            int r = 4 * warp + rr;
            long off = base + (long)(n0 + r0 + r) * 64;

            __half2 kk = reinterpret_cast<const __half2*>(gKh + off)[lane];
            __half2 vv = reinterpret_cast<const __half2*>(gVh + off)[lane];
            float2 kf = __half22float2(kk);
            float2 vf = __half22float2(vv);

            float ksum = kf.x + kf.y, ksq = kf.x * kf.x + kf.y * kf.y;
            float vsum = vf.x + vf.y, vsq = vf.x * vf.x + vf.y * vf.y;
#pragma unroll
            for (int o = 16; o > 0; o >>= 1) {
                ksum += __shfl_xor_sync(0xffffffffu, ksum, o);
                ksq  += __shfl_xor_sync(0xffffffffu, ksq, o);
                vsum += __shfl_xor_sync(0xffffffffu, vsum, o);
                vsq  += __shfl_xor_sync(0xffffffffu, vsq, o);
            }
            float kmu = ksum * (1.f / 64.f);
            float kvar = ksq * (1.f / 64.f) - kmu * kmu;
            float krs = rsqrtf(kvar + 1e-6f);
            float vmu = vsum * (1.f / 64.f);
            float vvar = vsq * (1.f / 64.f) - vmu * vmu;
            float vrs = rsqrtf(vvar + 1e-6f);

            float nk0 = (kf.x - kmu) * krs * sks[2 * lane]     + skb[2 * lane];
            float nk1 = (kf.y - kmu) * krs * sks[2 * lane + 1] + skb[2 * lane + 1];
            float nv0 = (vf.x - vmu) * vrs * svs[2 * lane]     + svb[2 * lane];
            float nv1 = (vf.y - vmu) * vrs * svs[2 * lane + 1] + svb[2 * lane + 1];

            *reinterpret_cast<__half2*>(&ksh[r][2 * lane]) = __floats2half2_rn(nk0, nk1);
            *reinterpret_cast<__half2*>(&vsh[r][2 * lane]) = __floats2half2_rn(nv0, nv1);
        }
        __syncthreads();

#pragma unroll
        for (int s = 0; s < 2; ++s) {
            uint32_t a[4], bq0[4], bq1[4];
            ldm4t(a, aaddr + s * rowstep);
            ldm4t(bq0, baddr0 + s * rowstep);
            ldm4t(bq1, baddr1 + s * rowstep);
            uint32_t bfr[4][2] = {{bq0[0], bq0[1]}, {bq0[2], bq0[3]},
                                  {bq1[0], bq1[1]}, {bq1[2], bq1[3]}};
#pragma unroll
            for (int nf = 0; nf < 4; ++nf)
                mma16816(acc[nf], a, bfr[nf]);
        }
    }

    float* p = gPpart + ((long)chunk * 64 + bh) * 4096;
    const int lrow = lane >> 2;
    const int lcol = (lane & 3) * 2;
#pragma unroll
    for (int nf = 0; nf < 4; ++nf) {
        int e = e0 + nf * 8 + lcol;
        *reinterpret_cast<float2*>(p + (d0 + lrow) * 64 + e) =
            make_float2(acc[nf][0], acc[nf][1]);
        *reinterpret_cast<float2*>(p + (d0 + lrow + 8) * 64 + e) =
            make_float2(acc[nf][2], acc[nf][3]);
    }
}

// reduce: fp32 p_attn output (required) + fp16 copy for out GEMM, float4 wide
__global__ void pattn_reduce_kernel(float* __restrict__ pout)
{
    int i4 = blockIdx.x * blockDim.x + threadIdx.x;    // 0..65535 (x4 elems)
    if (i4 >= 65536) return;
    const float4* part = reinterpret_cast<const float4*>(gPpart);
    float4 s = part[i4];
#pragma unroll
    for (int c = 1; c < NCHUNK; c++) {
        float4 v = part[(size_t)c * 65536 + i4];
        s.x += v.x; s.y += v.y; s.z += v.z; s.w += v.w;
    }
    s.x *= (1.f / 8192.f); s.y *= (1.f / 8192.f);
    s.z *= (1.f / 8192.f); s.w *= (1.f / 8192.f);
    reinterpret_cast<float4*>(pout)[i4] = s;
    __half2 h0 = __floats2half2_rn(s.x, s.y);
    __half2 h1 = __floats2half2_rn(s.z, s.w);
    reinterpret_cast<__half2*>(gPh)[2 * i4]     = h0;
    reinterpret_cast<__half2*>(gPh)[2 * i4 + 1] = h1;
}

// ---------------- out = Q @ P  (HMMA, fp16 inputs, fp32 out) -----------------
// Grid (64, 64): 64 n-tiles x 128 rows = 8192 rows per (b,h). 8 warps/block.
__global__ __launch_bounds__(256)
void out_kernel(float* __restrict__ out)
{
    const int bh = blockIdx.y;
    const int b = bh >> 4, h = bh & 15;
    const int n0 = blockIdx.x * 128;

    __shared__ __half psh[64][72];
    __shared__ __half qsh[128][72];

    const int t = threadIdx.x;
    const int warp = t >> 5, lane = t & 31;

    const __half* P = gPh + (size_t)bh * 4096;
    for (int i = t; i < 2048; i += 256) {            // P: 64x64, half2 units
        int d = i >> 5, e2 = (i & 31) * 2;
        *reinterpret_cast<__half2*>(&psh[d][e2]) =
            *reinterpret_cast<const __half2*>(P + d * 64 + e2);
    }
    const size_t base = (size_t)b * (Ss * Ff) + (size_t)h * 524288 + (size_t)n0 * 64;
    for (int i = t; i < 2048; i += 256) {            // Q: 128x64, 4-half units
        int n = i >> 4, d4 = (i & 15) * 4;
        *reinterpret_cast<uint2*>(&qsh[n][d4]) =
            *reinterpret_cast<const uint2*>(gQh + base + (size_t)n * 64 + d4);
    }
    __syncthreads();

    const int arow = (lane & 7) + ((lane >> 3) & 1) * 8;
    const int ao = ((lane >> 4) & 1) * 8;            // halves
    const int brow = (lane & 7) + ((lane >> 3) & 1) * 8;
    const int bo = ((lane >> 4) & 1) * 8;

    float acc[8][4];
#pragma unroll
    for (int i = 0; i < 8; i++)
#pragma unroll
        for (int q = 0; q < 4; q++) acc[i][q] = 0.f;

#pragma unroll
    for (int s = 0; s < 4; ++s) {                    // k = d, 4 steps of 16
        uint32_t a[4];
        ldm4(a, smem_u32(&qsh[warp * 16 + arow][s * 16 + ao]));
        uint32_t bfr[8][2];
#pragma unroll
        for (int g = 0; g < 4; ++g) {                // e groups of 16
            uint32_t r[4];
            ldm4t(r, smem_u32(&psh[s * 16 + brow][g * 16 + bo]));
            bfr[2 * g][0] = r[0]; bfr[2 * g][1] = r[1];
            bfr[2 * g + 1][0] = r[2]; bfr[2 * g + 1][1] = r[3];
        }
#pragma unroll
        for (int nf = 0; nf < 8; ++nf)
            mma16816(acc[nf], a, bfr[nf]);
    }

    const int lrow = lane >> 2;
    const int lcol = (lane & 3) * 2;
#pragma unroll
    for (int nf = 0; nf < 8; ++nf) {
        int e = nf * 8 + lcol;
        *reinterpret_cast<float2*>(out + base + (size_t)(warp * 16 + lrow) * 64 + e) =
            make_float2(acc[nf][0], acc[nf][1]);
        *reinterpret_cast<float2*>(out + base + (size_t)(warp * 16 + lrow + 8) * 64 + e) =
            make_float2(acc[nf][2], acc[nf][3]);
    }
}

// ---------------- launch ----------------------------------------------------
extern "C" void kernel_launch(void* const* d_in, const int* in_sizes, int n_in,
                              void* d_out, int out_size)
{
    (void)in_sizes; (void)n_in; (void)out_size;
    const float* query = (const float*)d_in[0];
    const float* key   = (const float*)d_in[1];
    const float* value = (const float*)d_in[2];
    const float* Wq    = (const float*)d_in[3];
    const float* Wk    = (const float*)d_in[4];
    const float* Wv    = (const float*)d_in[5];
    const float* lnk_s = (const float*)d_in[6];
    const float* lnk_b = (const float*)d_in[7];
    const float* lnv_s = (const float*)d_in[8];
    const float* lnv_b = (const float*)d_in[9];

    float* out = (float*)d_out;
    float* pout = out + QELEMS;

    cudaFuncSetAttribute(gemm_mma_kernel, cudaFuncAttributeMaxDynamicSharedMemorySize,
                         3 * STAGE + 1024);

    convert_A_kernel<<<dim3(16384, 3), 256>>>(query, key, value);
    convert_W_kernel<<<dim3(32, 32, 3), 256>>>(Wq, Wk, Wv);

    gemm_mma_kernel<<<dim3(8, 256, 3), 256, 3 * STAGE + 1024>>>();

    dim3 pgrid(64, NCHUNK);
    pattn_partial_kernel<<<pgrid, 256>>>(lnk_s, lnk_b, lnv_s, lnv_b);
    pattn_reduce_kernel<<<(65536 + 255) / 256, 256>>>(pout);

    out_kernel<<<dim3(64, 64), 256>>>(out);
}

// round 14
// speedup vs baseline: 1.0180x; 1.0180x over previous
#include <cuda_runtime.h>
#include <cuda_fp16.h>
#include <cstdint>

// ---------------- problem constants ----------------
static constexpr int Bb = 4, Ss = 8192, Ff = 1024, Hh = 16, Dd = 64;
static constexpr int Mm = Bb * Ss;              // 32768
static constexpr int Kk = 1024, Nn = 1024;
static constexpr long QELEMS = (long)Mm * Ff;   // 33554432
static constexpr int NCHUNK = 32;
static constexpr int ROWS_PER_CHUNK = 8192 / NCHUNK;  // 256

// ---------------- scratch (device globals) ----------------
__device__ __half gQh[33554432];                // Q projection, fp16
__device__ __half gKh[33554432];                // K projection, fp16
__device__ __half gVh[33554432];                // V projection, fp16
__device__ float gPpart[(long)NCHUNK * 64 * 4096];
__device__ __half gPh[64 * 4096];               // fp16 copy of p_attn for out HMMA
__device__ __half gAh[3L * 33554432];
__device__ __half gWt[3L * 1048576];            // W^T: [n][k], k contiguous, fp16

// ---------------- helpers ----------------
__device__ __forceinline__ uint32_t smem_u32(const void* p) {
    uint32_t a;
    asm("{ .reg .u64 t; cvta.to.shared.u64 t, %1; cvt.u32.u64 %0, t; }" : "=r"(a) : "l"(p));
    return a;
}
// Swizzle<3,4,3> for 128B rows: XOR 16B-chunk bits [4:6] with row bits [7:9]
__device__ __forceinline__ uint32_t SZ128(uint32_t a) { return a ^ ((a >> 3) & 0x70u); }

__device__ __forceinline__ void cp16(uint32_t dst, const void* src) {
    asm volatile("cp.async.cg.shared.global [%0], [%1], 16;\n" :: "r"(dst), "l"(src));
}
__device__ __forceinline__ void cp_commit() { asm volatile("cp.async.commit_group;\n"); }
template<int N> __device__ __forceinline__ void cp_wait() {
    asm volatile("cp.async.wait_group %0;\n" :: "n"(N));
}
__device__ __forceinline__ void ldm4(uint32_t* r, uint32_t addr) {
    asm volatile("ldmatrix.sync.aligned.m8n8.x4.shared.b16 {%0,%1,%2,%3}, [%4];"
                 : "=r"(r[0]), "=r"(r[1]), "=r"(r[2]), "=r"(r[3]) : "r"(addr));
}
__device__ __forceinline__ void ldm4t(uint32_t* r, uint32_t addr) {
    asm volatile("ldmatrix.sync.aligned.m8n8.x4.trans.shared.b16 {%0,%1,%2,%3}, [%4];"
                 : "=r"(r[0]), "=r"(r[1]), "=r"(r[2]), "=r"(r[3]) : "r"(addr));
}
__device__ __forceinline__ void mma16816(float* d, const uint32_t* a, const uint32_t* b) {
    asm volatile(
        "mma.sync.aligned.m16n8k16.row.col.f32.f16.f16.f32 "
        "{%0,%1,%2,%3}, {%4,%5,%6,%7}, {%8,%9}, {%0,%1,%2,%3};"
        : "+f"(d[0]), "+f"(d[1]), "+f"(d[2]), "+f"(d[3])
        : "r"(a[0]), "r"(a[1]), "r"(a[2]), "r"(a[3]), "r"(b[0]), "r"(b[1]));
}

// ---------------- conversion prepasses ----------------
__global__ __launch_bounds__(256)
void convert_A_kernel(const float* __restrict__ q, const float* __restrict__ k,
                      const float* __restrict__ v)
{
    const int which = blockIdx.y;
    const float* src = (which == 0) ? q : (which == 1) ? k : v;
    __half* hi = gAh + (size_t)which * 33554432;

    size_t i8 = (size_t)blockIdx.x * blockDim.x + threadIdx.x;   // 0..4194303
    float4 x0 = reinterpret_cast<const float4*>(src)[2 * i8];
    float4 x1 = reinterpret_cast<const float4*>(src)[2 * i8 + 1];

    __half2 a0 = __halves2half2(__float2half_rn(x0.x), __float2half_rn(x0.y));
    __half2 a1 = __halves2half2(__float2half_rn(x0.z), __float2half_rn(x0.w));
    __half2 a2 = __halves2half2(__float2half_rn(x1.x), __float2half_rn(x1.y));
    __half2 a3 = __halves2half2(__float2half_rn(x1.z), __float2half_rn(x1.w));
    uint4 u;
    u.x = *reinterpret_cast<unsigned*>(&a0);
    u.y = *reinterpret_cast<unsigned*>(&a1);
    u.z = *reinterpret_cast<unsigned*>(&a2);
    u.w = *reinterpret_cast<unsigned*>(&a3);
    reinterpret_cast<uint4*>(hi)[i8] = u;
}

__global__ __launch_bounds__(256)
void convert_W_kernel(const float* __restrict__ wq, const float* __restrict__ wk,
                      const float* __restrict__ wv)
{
    const int which = blockIdx.z;
    const float* W = (which == 0) ? wq : (which == 1) ? wk : wv;
    __half* hi = gWt + (size_t)which * 1048576;

    __shared__ float tile[32][33];
    const int bx = blockIdx.x * 32;   // n block
    const int by = blockIdx.y * 32;   // k block
    const int tx = threadIdx.x & 31;
    const int ty = threadIdx.x >> 5;  // 0..7

#pragma unroll
    for (int i = 0; i < 32; i += 8)
        tile[ty + i][tx] = W[(size_t)(by + ty + i) * 1024 + bx + tx];
    __syncthreads();
#pragma unroll
    for (int i = 0; i < 32; i += 8) {
        float x = tile[tx][ty + i];                 // = W[by+tx][bx+ty+i]
        size_t o = (size_t)(bx + ty + i) * 1024 + by + tx;   // Wt[n][k]
        hi[o] = __float2half_rn(x);
    }
}

// ---------------- HMMA GEMM: C[M,N] = A @ W  (fp16, 3-stage, occ 2) ----------
// Tile 128x128xK64, 8 warps (2m x 4n, 64x32 warp tiles), 3-stage cp.async.
static constexpr int STAGE = 32768;
static constexpr int NCH = 16;        // 1024 / 64

__global__ __launch_bounds__(256, 2)
void gemm_mma_kernel(int which_base)
{
    extern __shared__ char smem[];
    const int which = which_base + blockIdx.z;
    const int n0 = blockIdx.x * 128;
    const int m0 = blockIdx.y * 128;
    const int tid = threadIdx.x;
    const int wid = tid >> 5, lane = tid & 31;

    const uint32_t tiles = (smem_u32(smem) + 1023) & ~1023u;

    const __half* Ah = gAh + (size_t)which * 33554432;
    const __half* Bp = gWt + (size_t)which * 1048576;

    const int mbase_w = (wid & 1) * 64;
    const int nbase_w = (wid >> 1) * 32;

    float acc[4][4][4];
#pragma unroll
    for (int i = 0; i < 4; i++)
#pragma unroll
        for (int j = 0; j < 4; j++)
#pragma unroll
            for (int q = 0; q < 4; q++) acc[i][j][q] = 0.f;

    auto load_chunk = [&](int buf, int c) {
        const uint32_t base = tiles + buf * STAGE;
        const int k0 = c * 64;
#pragma unroll
        for (int i = tid; i < 1024; i += 256) {         // A: 128 rows x 8 chunks
            int r = i >> 3, c8 = i & 7;
            size_t gb = ((size_t)(m0 + r) * 1024 + k0 + c8 * 8) * 2;
            uint32_t d = SZ128((uint32_t)(r * 128 + c8 * 16));
            cp16(base + d, (const char*)Ah + gb);
        }
#pragma unroll
        for (int i = tid; i < 1024; i += 256) {         // B: 128 rows x 8 chunks
            int r = i >> 3, c8 = i & 7;
            size_t gb = ((size_t)(n0 + r) * 1024 + k0 + c8 * 8) * 2;
            uint32_t d = SZ128((uint32_t)(r * 128 + c8 * 16));
            cp16(base + 16384 + d, (const char*)Bp + gb);
        }
        cp_commit();
    };

    load_chunk(0, 0);
    load_chunk(1, 1);

    const int arow = (lane & 7) + ((lane >> 3) & 1) * 8;
    const int aoff = ((lane >> 4) & 1) * 16;
    const int brow = (lane & 7) + ((lane >> 4) & 1) * 8;
    const int boff = ((lane >> 3) & 1) * 16;

    int buf = 0;
    for (int c = 0; c < NCH; ++c) {
        if (c < NCH - 1) cp_wait<1>(); else cp_wait<0>();
        __syncthreads();
        if (c + 2 < NCH) load_chunk((buf + 2) % 3, c + 2);

        const uint32_t ab = tiles + buf * STAGE;
        const uint32_t bb = ab + 16384;

#pragma unroll
        for (int s = 0; s < 4; ++s) {
            uint32_t ah[4][4], bh2[4][2];
#pragma unroll
            for (int bg = 0; bg < 2; ++bg) {
                uint32_t u = SZ128((uint32_t)((nbase_w + bg * 16 + brow) * 128 + s * 32 + boff));
                uint32_t r[4];
                ldm4(r, bb + u);
                bh2[2 * bg][0] = r[0]; bh2[2 * bg][1] = r[1];
                bh2[2 * bg + 1][0] = r[2]; bh2[2 * bg + 1][1] = r[3];
            }
#pragma unroll
            for (int mf = 0; mf < 4; ++mf) {
                uint32_t u = SZ128((uint32_t)((mbase_w + mf * 16 + arow) * 128 + s * 32 + aoff));
                ldm4(ah[mf], ab + u);
            }
#pragma unroll
            for (int mf = 0; mf < 4; ++mf)
#pragma unroll
                for (int nf = 0; nf < 4; ++nf)
                    mma16816(acc[mf][nf], ah[mf], bh2[nf]);
        }
        buf = (buf + 1) % 3;
    }

    // epilogue: all projections stored fp16
    __half* Ch = (which == 0) ? gQh : (which == 1) ? gKh : gVh;
    const int lrow = lane >> 2;
    const int lcol = (lane & 3) * 2;
#pragma unroll
    for (int mf = 0; mf < 4; ++mf)
#pragma unroll
        for (int nf = 0; nf < 4; ++nf) {
            int rm = m0 + mbase_w + mf * 16 + lrow;
            int cn = n0 + nbase_w + nf * 8 + lcol;
            *reinterpret_cast<__half2*>(Ch + (size_t)rm * 1024 + cn) =
                __floats2half2_rn(acc[mf][nf][0], acc[mf][nf][1]);
            *reinterpret_cast<__half2*>(Ch + (size_t)(rm + 8) * 1024 + cn) =
                __floats2half2_rn(acc[mf][nf][2], acc[mf][nf][3]);
        }
}

// ---------------- p_attn partials: LN(K)^T LN(V), HMMA consumer --------------
// 16 rows staged per iteration (2 rows/warp) — R12-validated schedule.
__global__ __launch_bounds__(256)
void pattn_partial_kernel(const float* __restrict__ lnk_s, const float* __restrict__ lnk_b,
                          const float* __restrict__ lnv_s, const float* __restrict__ lnv_b)
{
    const int bh = blockIdx.x;
    const int chunk = blockIdx.y;
    const int b = bh >> 4, h = bh & 15;
    const int n0 = chunk * ROWS_PER_CHUNK;
    const long base = (long)b * (Ss * Ff) + (long)h * (512 * 1024);

    __shared__ __half ksh[16][72];
    __shared__ __half vsh[16][72];
    __shared__ float sks[64], skb[64], svs[64], svb[64];

    const int t = threadIdx.x;
    const int warp = t >> 5, lane = t & 31;

    if (t < 64) {
        sks[t] = lnk_s[h * 64 + t];
        skb[t] = lnk_b[h * 64 + t];
        svs[t] = lnv_s[h * 64 + t];
        svb[t] = lnv_b[h * 64 + t];
    }

    const int d0 = (warp >> 1) * 16;
    const int e0 = (warp & 1) * 32;

    const uint32_t aaddr = smem_u32(
        &ksh[(lane & 7) + ((lane >> 4) & 1) * 8][d0 + ((lane >> 3) & 1) * 8]);
    const uint32_t baddr0 = smem_u32(
        &vsh[(lane & 7) + ((lane >> 3) & 1) * 8][e0 + ((lane >> 4) & 1) * 8]);
    const uint32_t baddr1 = baddr0 + 16 * 2;

    float acc[4][4];
#pragma unroll
    for (int i = 0; i < 4; i++)
#pragma unroll
        for (int j = 0; j < 4; j++) acc[i][j] = 0.f;

    for (int r0 = 0; r0 < ROWS_PER_CHUNK; r0 += 16) {
        __syncthreads();
#pragma unroll
        for (int rr = 0; rr < 2; rr++) {
            int r = 2 * warp + rr;
            long off = base + (long)(n0 + r0 + r) * 64;

            __half2 kk = reinterpret_cast<const __half2*>(gKh + off)[lane];
            __half2 vv = reinterpret_cast<const __half2*>(gVh + off)[lane];
            float2 kf = __half22float2(kk);
            float2 vf = __half22float2(vv);

            float ksum = kf.x + kf.y, ksq = kf.x * kf.x + kf.y * kf.y;
            float vsum = vf.x + vf.y, vsq = vf.x * vf.x + vf.y * vf.y;
#pragma unroll
            for (int o = 16; o > 0; o >>= 1) {
                ksum += __shfl_xor_sync(0xffffffffu, ksum, o);
                ksq  += __shfl_xor_sync(0xffffffffu, ksq, o);
                vsum += __shfl_xor_sync(0xffffffffu, vsum, o);
                vsq  += __shfl_xor_sync(0xffffffffu, vsq, o);
            }
            float kmu = ksum * (1.f / 64.f);
            float kvar = ksq * (1.f / 64.f) - kmu * kmu;
            float krs = rsqrtf(kvar + 1e-6f);
            float vmu = vsum * (1.f / 64.f);
            float vvar = vsq * (1.f / 64.f) - vmu * vmu;
            float vrs = rsqrtf(vvar + 1e-6f);

            float nk0 = (kf.x - kmu) * krs * sks[2 * lane]     + skb[2 * lane];
            float nk1 = (kf.y - kmu) * krs * sks[2 * lane + 1] + skb[2 * lane + 1];
            float nv0 = (vf.x - vmu) * vrs * svs[2 * lane]     + svb[2 * lane];
            float nv1 = (vf.y - vmu) * vrs * svs[2 * lane + 1] + svb[2 * lane + 1];

            *reinterpret_cast<__half2*>(&ksh[r][2 * lane]) = __floats2half2_rn(nk0, nk1);
            *reinterpret_cast<__half2*>(&vsh[r][2 * lane]) = __floats2half2_rn(nv0, nv1);
        }
        __syncthreads();

        uint32_t a[4], bq0[4], bq1[4];
        ldm4t(a, aaddr);
        ldm4t(bq0, baddr0);
        ldm4t(bq1, baddr1);
        uint32_t bfr[4][2] = {{bq0[0], bq0[1]}, {bq0[2], bq0[3]},
                              {bq1[0], bq1[1]}, {bq1[2], bq1[3]}};
#pragma unroll
        for (int nf = 0; nf < 4; ++nf)
            mma16816(acc[nf], a, bfr[nf]);
    }

    float* p = gPpart + ((long)chunk * 64 + bh) * 4096;
    const int lrow = lane >> 2;
    const int lcol = (lane & 3) * 2;
#pragma unroll
    for (int nf = 0; nf < 4; ++nf) {
        int e = e0 + nf * 8 + lcol;
        *reinterpret_cast<float2*>(p + (d0 + lrow) * 64 + e) =
            make_float2(acc[nf][0], acc[nf][1]);
        *reinterpret_cast<float2*>(p + (d0 + lrow + 8) * 64 + e) =
            make_float2(acc[nf][2], acc[nf][3]);
    }
}

// reduce: fp32 p_attn output (required) + fp16 copy for out GEMM, float4 wide
__global__ void pattn_reduce_kernel(float* __restrict__ pout)
{
    int i4 = blockIdx.x * blockDim.x + threadIdx.x;    // 0..65535 (x4 elems)
    if (i4 >= 65536) return;
    const float4* part = reinterpret_cast<const float4*>(gPpart);
    float4 s = part[i4];
#pragma unroll
    for (int c = 1; c < NCHUNK; c++) {
        float4 v = part[(size_t)c * 65536 + i4];
        s.x += v.x; s.y += v.y; s.z += v.z; s.w += v.w;
    }
    s.x *= (1.f / 8192.f); s.y *= (1.f / 8192.f);
    s.z *= (1.f / 8192.f); s.w *= (1.f / 8192.f);
    reinterpret_cast<float4*>(pout)[i4] = s;
    __half2 h0 = __floats2half2_rn(s.x, s.y);
    __half2 h1 = __floats2half2_rn(s.z, s.w);
    reinterpret_cast<__half2*>(gPh)[2 * i4]     = h0;
    reinterpret_cast<__half2*>(gPh)[2 * i4 + 1] = h1;
}

// ---------------- out = Q @ P  (HMMA, fp16 inputs, fp32 out) -----------------
// Grid (64, 64): 64 n-tiles x 128 rows = 8192 rows per (b,h). 8 warps/block.
__global__ __launch_bounds__(256)
void out_kernel(float* __restrict__ out)
{
    const int bh = blockIdx.y;
    const int b = bh >> 4, h = bh & 15;
    const int n0 = blockIdx.x * 128;

    __shared__ __half psh[64][72];
    __shared__ __half qsh[128][72];

    const int t = threadIdx.x;
    const int warp = t >> 5, lane = t & 31;

    const __half* P = gPh + (size_t)bh * 4096;
    for (int i = t; i < 2048; i += 256) {            // P: 64x64, half2 units
        int d = i >> 5, e2 = (i & 31) * 2;
        *reinterpret_cast<__half2*>(&psh[d][e2]) =
            *reinterpret_cast<const __half2*>(P + d * 64 + e2);
    }
    const size_t base = (size_t)b * (Ss * Ff) + (size_t)h * 524288 + (size_t)n0 * 64;
    for (int i = t; i < 2048; i += 256) {            // Q: 128x64, 4-half units
        int n = i >> 4, d4 = (i & 15) * 4;
        *reinterpret_cast<uint2*>(&qsh[n][d4]) =
            *reinterpret_cast<const uint2*>(gQh + base + (size_t)n * 64 + d4);
    }
    __syncthreads();

    const int arow = (lane & 7) + ((lane >> 3) & 1) * 8;
    const int ao = ((lane >> 4) & 1) * 8;            // halves
    const int brow = (lane & 7) + ((lane >> 3) & 1) * 8;
    const int bo = ((lane >> 4) & 1) * 8;

    float acc[8][4];
#pragma unroll
    for (int i = 0; i < 8; i++)
#pragma unroll
        for (int q = 0; q < 4; q++) acc[i][q] = 0.f;

#pragma unroll
    for (int s = 0; s < 4; ++s) {                    // k = d, 4 steps of 16
        uint32_t a[4];
        ldm4(a, smem_u32(&qsh[warp * 16 + arow][s * 16 + ao]));
        uint32_t bfr[8][2];
#pragma unroll
        for (int g = 0; g < 4; ++g) {                // e groups of 16
            uint32_t r[4];
            ldm4t(r, smem_u32(&psh[s * 16 + brow][g * 16 + bo]));
            bfr[2 * g][0] = r[0]; bfr[2 * g][1] = r[1];
            bfr[2 * g + 1][0] = r[2]; bfr[2 * g + 1][1] = r[3];
        }
#pragma unroll
        for (int nf = 0; nf < 8; ++nf)
            mma16816(acc[nf], a, bfr[nf]);
    }

    const int lrow = lane >> 2;
    const int lcol = (lane & 3) * 2;
#pragma unroll
    for (int nf = 0; nf < 8; ++nf) {
        int e = nf * 8 + lcol;
        *reinterpret_cast<float2*>(out + base + (size_t)(warp * 16 + lrow) * 64 + e) =
            make_float2(acc[nf][0], acc[nf][1]);
        *reinterpret_cast<float2*>(out + base + (size_t)(warp * 16 + lrow + 8) * 64 + e) =
            make_float2(acc[nf][2], acc[nf][3]);
    }
}

// ---------------- launch ----------------------------------------------------
extern "C" void kernel_launch(void* const* d_in, const int* in_sizes, int n_in,
                              void* d_out, int out_size)
{
    (void)in_sizes; (void)n_in; (void)out_size;
    const float* query = (const float*)d_in[0];
    const float* key   = (const float*)d_in[1];
    const float* value = (const float*)d_in[2];
    const float* Wq    = (const float*)d_in[3];
    const float* Wk    = (const float*)d_in[4];
    const float* Wv    = (const float*)d_in[5];
    const float* lnk_s = (const float*)d_in[6];
    const float* lnk_b = (const float*)d_in[7];
    const float* lnv_s = (const float*)d_in[8];
    const float* lnv_b = (const float*)d_in[9];

    float* out = (float*)d_out;
    float* pout = out + QELEMS;

    // persistent side stream + events (created on first call, outside capture;
    // the captured work sequence is identical on every call)
    static cudaStream_t s2 = nullptr;
    static cudaEvent_t evFork = nullptr, evJoin = nullptr;
    if (s2 == nullptr) {
        cudaStreamCreateWithFlags(&s2, cudaStreamNonBlocking);
        cudaEventCreateWithFlags(&evFork, cudaEventDisableTiming);
        cudaEventCreateWithFlags(&evJoin, cudaEventDisableTiming);
        cudaFuncSetAttribute(gemm_mma_kernel,
                             cudaFuncAttributeMaxDynamicSharedMemorySize,
                             3 * STAGE + 1024);
    }

    convert_A_kernel<<<dim3(16384, 3), 256>>>(query, key, value);
    convert_W_kernel<<<dim3(32, 32, 3), 256>>>(Wq, Wk, Wv);

    // K and V projections first (pattn chain depends on them)
    gemm_mma_kernel<<<dim3(8, 256, 2), 256, 3 * STAGE + 1024>>>(1);

    // fork: Q projection on side stream, pattn chain on main stream
    cudaEventRecord(evFork, 0);
    cudaStreamWaitEvent(s2, evFork, 0);
    gemm_mma_kernel<<<dim3(8, 256, 1), 256, 3 * STAGE + 1024, s2>>>(0);

    dim3 pgrid(64, NCHUNK);
    pattn_partial_kernel<<<pgrid, 256>>>(lnk_s, lnk_b, lnv_s, lnv_b);
    pattn_reduce_kernel<<<(65536 + 255) / 256, 256>>>(pout);

    // join: out needs gQh (s2) and gPh (main)
    cudaEventRecord(evJoin, s2);
    cudaStreamWaitEvent(0, evJoin, 0);

    out_kernel<<<dim3(64, 64), 256>>>(out);
}

// round 15
// speedup vs baseline: 1.0228x; 1.0047x over previous
#include <cuda_runtime.h>
#include <cuda_fp16.h>
#include <cstdint>

// ---------------- problem constants ----------------
static constexpr int Bb = 4, Ss = 8192, Ff = 1024, Hh = 16, Dd = 64;
static constexpr int Mm = Bb * Ss;              // 32768
static constexpr int Kk = 1024, Nn = 1024;
static constexpr long QELEMS = (long)Mm * Ff;   // 33554432
static constexpr int NCHUNK = 32;
static constexpr int ROWS_PER_CHUNK = 8192 / NCHUNK;  // 256

// ---------------- scratch (device globals) ----------------
__device__ __half gQh[33554432];                // Q projection, fp16
__device__ __half gKh[33554432];                // K projection, fp16
__device__ __half gVh[33554432];                // V projection, fp16
__device__ float gPpart[(long)NCHUNK * 64 * 4096];
__device__ __half gPh[64 * 4096];               // fp16 copy of p_attn for out HMMA
__device__ __half gAh[3L * 33554432];
__device__ __half gWt[3L * 1048576];            // W^T: [n][k], k contiguous, fp16

// ---------------- helpers ----------------
__device__ __forceinline__ uint32_t smem_u32(const void* p) {
    uint32_t a;
    asm("{ .reg .u64 t; cvta.to.shared.u64 t, %1; cvt.u32.u64 %0, t; }" : "=r"(a) : "l"(p));
    return a;
}
// Swizzle<3,4,3> for 128B rows: XOR 16B-chunk bits [4:6] with row bits [7:9]
__device__ __forceinline__ uint32_t SZ128(uint32_t a) { return a ^ ((a >> 3) & 0x70u); }

__device__ __forceinline__ void cp16(uint32_t dst, const void* src) {
    asm volatile("cp.async.cg.shared.global [%0], [%1], 16;\n" :: "r"(dst), "l"(src));
}
__device__ __forceinline__ void cp_commit() { asm volatile("cp.async.commit_group;\n"); }
template<int N> __device__ __forceinline__ void cp_wait() {
    asm volatile("cp.async.wait_group %0;\n" :: "n"(N));
}
__device__ __forceinline__ void ldm4(uint32_t* r, uint32_t addr) {
    asm volatile("ldmatrix.sync.aligned.m8n8.x4.shared.b16 {%0,%1,%2,%3}, [%4];"
                 : "=r"(r[0]), "=r"(r[1]), "=r"(r[2]), "=r"(r[3]) : "r"(addr));
}
__device__ __forceinline__ void ldm4t(uint32_t* r, uint32_t addr) {
    asm volatile("ldmatrix.sync.aligned.m8n8.x4.trans.shared.b16 {%0,%1,%2,%3}, [%4];"
                 : "=r"(r[0]), "=r"(r[1]), "=r"(r[2]), "=r"(r[3]) : "r"(addr));
}
__device__ __forceinline__ void mma16816(float* d, const uint32_t* a, const uint32_t* b) {
    asm volatile(
        "mma.sync.aligned.m16n8k16.row.col.f32.f16.f16.f32 "
        "{%0,%1,%2,%3}, {%4,%5,%6,%7}, {%8,%9}, {%0,%1,%2,%3};"
        : "+f"(d[0]), "+f"(d[1]), "+f"(d[2]), "+f"(d[3])
        : "r"(a[0]), "r"(a[1]), "r"(a[2]), "r"(a[3]), "r"(b[0]), "r"(b[1]));
}

// ---------------- conversion prepasses ----------------
__global__ __launch_bounds__(256)
void convert_A_kernel(const float* __restrict__ q, const float* __restrict__ k,
                      const float* __restrict__ v)
{
    const int which = blockIdx.y;
    const float* src = (which == 0) ? q : (which == 1) ? k : v;
    __half* hi = gAh + (size_t)which * 33554432;

    size_t i8 = (size_t)blockIdx.x * blockDim.x + threadIdx.x;   // 0..4194303
    float4 x0 = reinterpret_cast<const float4*>(src)[2 * i8];
    float4 x1 = reinterpret_cast<const float4*>(src)[2 * i8 + 1];

    __half2 a0 = __halves2half2(__float2half_rn(x0.x), __float2half_rn(x0.y));
    __half2 a1 = __halves2half2(__float2half_rn(x0.z), __float2half_rn(x0.w));
    __half2 a2 = __halves2half2(__float2half_rn(x1.x), __float2half_rn(x1.y));
    __half2 a3 = __halves2half2(__float2half_rn(x1.z), __float2half_rn(x1.w));
    uint4 u;
    u.x = *reinterpret_cast<unsigned*>(&a0);
    u.y = *reinterpret_cast<unsigned*>(&a1);
    u.z = *reinterpret_cast<unsigned*>(&a2);
    u.w = *reinterpret_cast<unsigned*>(&a3);
    reinterpret_cast<uint4*>(hi)[i8] = u;
}

__global__ __launch_bounds__(256)
void convert_W_kernel(const float* __restrict__ wq, const float* __restrict__ wk,
                      const float* __restrict__ wv)
{
    const int which = blockIdx.z;
    const float* W = (which == 0) ? wq : (which == 1) ? wk : wv;
    __half* hi = gWt + (size_t)which * 1048576;

    __shared__ float tile[32][33];
    const int bx = blockIdx.x * 32;   // n block
    const int by = blockIdx.y * 32;   // k block
    const int tx = threadIdx.x & 31;
    const int ty = threadIdx.x >> 5;  // 0..7

#pragma unroll
    for (int i = 0; i < 32; i += 8)
        tile[ty + i][tx] = W[(size_t)(by + ty + i) * 1024 + bx + tx];
    __syncthreads();
#pragma unroll
    for (int i = 0; i < 32; i += 8) {
        float x = tile[tx][ty + i];                 // = W[by+tx][bx+ty+i]
        size_t o = (size_t)(bx + ty + i) * 1024 + by + tx;   // Wt[n][k]
        hi[o] = __float2half_rn(x);
    }
}

// ---------------- HMMA GEMM: C[M,N] = A @ W  (fp16, 3-stage) -----------------
// Tile 128x128xK64, 4 warps (2m x 2n), 64x64 warp tiles, occ 2.
// Warp-tile widening halves A-fragment smem-read redundancy (crossbar bound).
static constexpr int STAGE = 32768;
static constexpr int NCH = 16;        // 1024 / 64

__global__ __launch_bounds__(128, 2)
void gemm_mma_kernel(int which_base)
{
    extern __shared__ char smem[];
    const int which = which_base + blockIdx.z;
    const int n0 = blockIdx.x * 128;
    const int m0 = blockIdx.y * 128;
    const int tid = threadIdx.x;
    const int wid = tid >> 5, lane = tid & 31;

    const uint32_t tiles = (smem_u32(smem) + 1023) & ~1023u;

    const __half* Ah = gAh + (size_t)which * 33554432;
    const __half* Bp = gWt + (size_t)which * 1048576;

    const int mbase_w = (wid & 1) * 64;
    const int nbase_w = (wid >> 1) * 64;

    float acc[4][8][4];
#pragma unroll
    for (int i = 0; i < 4; i++)
#pragma unroll
        for (int j = 0; j < 8; j++)
#pragma unroll
            for (int q = 0; q < 4; q++) acc[i][j][q] = 0.f;

    auto load_chunk = [&](int buf, int c) {
        const uint32_t base = tiles + buf * STAGE;
        const int k0 = c * 64;
#pragma unroll
        for (int i = tid; i < 1024; i += 128) {         // A: 128 rows x 8 chunks
            int r = i >> 3, c8 = i & 7;
            size_t gb = ((size_t)(m0 + r) * 1024 + k0 + c8 * 8) * 2;
            uint32_t d = SZ128((uint32_t)(r * 128 + c8 * 16));
            cp16(base + d, (const char*)Ah + gb);
        }
#pragma unroll
        for (int i = tid; i < 1024; i += 128) {         // B: 128 rows x 8 chunks
            int r = i >> 3, c8 = i & 7;
            size_t gb = ((size_t)(n0 + r) * 1024 + k0 + c8 * 8) * 2;
            uint32_t d = SZ128((uint32_t)(r * 128 + c8 * 16));
            cp16(base + 16384 + d, (const char*)Bp + gb);
        }
        cp_commit();
    };

    load_chunk(0, 0);
    load_chunk(1, 1);

    const int arow = (lane & 7) + ((lane >> 3) & 1) * 8;
    const int aoff = ((lane >> 4) & 1) * 16;
    const int brow = (lane & 7) + ((lane >> 4) & 1) * 8;
    const int boff = ((lane >> 3) & 1) * 16;

    int buf = 0;
    for (int c = 0; c < NCH; ++c) {
        if (c < NCH - 1) cp_wait<1>(); else cp_wait<0>();
        __syncthreads();
        if (c + 2 < NCH) load_chunk((buf + 2) % 3, c + 2);

        const uint32_t ab = tiles + buf * STAGE;
        const uint32_t bb = ab + 16384;

#pragma unroll
        for (int s = 0; s < 4; ++s) {
            uint32_t ah[4][4], bh2[8][2];
#pragma unroll
            for (int bg = 0; bg < 4; ++bg) {            // 4 x 16-col B groups = 64 n
                uint32_t u = SZ128((uint32_t)((nbase_w + bg * 16 + brow) * 128 + s * 32 + boff));
                uint32_t r[4];
                ldm4(r, bb + u);
                bh2[2 * bg][0] = r[0]; bh2[2 * bg][1] = r[1];
                bh2[2 * bg + 1][0] = r[2]; bh2[2 * bg + 1][1] = r[3];
            }
#pragma unroll
            for (int mf = 0; mf < 4; ++mf) {
                uint32_t u = SZ128((uint32_t)((mbase_w + mf * 16 + arow) * 128 + s * 32 + aoff));
                ldm4(ah[mf], ab + u);
            }
#pragma unroll
            for (int mf = 0; mf < 4; ++mf)
#pragma unroll
                for (int nf = 0; nf < 8; ++nf)
                    mma16816(acc[mf][nf], ah[mf], bh2[nf]);
        }
        buf = (buf + 1) % 3;
    }

    // epilogue: all projections stored fp16
    __half* Ch = (which == 0) ? gQh : (which == 1) ? gKh : gVh;
    const int lrow = lane >> 2;
    const int lcol = (lane & 3) * 2;
#pragma unroll
    for (int mf = 0; mf < 4; ++mf)
#pragma unroll
        for (int nf = 0; nf < 8; ++nf) {
            int rm = m0 + mbase_w + mf * 16 + lrow;
            int cn = n0 + nbase_w + nf * 8 + lcol;
            *reinterpret_cast<__half2*>(Ch + (size_t)rm * 1024 + cn) =
                __floats2half2_rn(acc[mf][nf][0], acc[mf][nf][1]);
            *reinterpret_cast<__half2*>(Ch + (size_t)(rm + 8) * 1024 + cn) =
                __floats2half2_rn(acc[mf][nf][2], acc[mf][nf][3]);
        }
}

// ---------------- p_attn partials: LN(K)^T LN(V), HMMA consumer --------------
// 16 rows staged per iteration (2 rows/warp) — R12-validated schedule.
__global__ __launch_bounds__(256)
void pattn_partial_kernel(const float* __restrict__ lnk_s, const float* __restrict__ lnk_b,
                          const float* __restrict__ lnv_s, const float* __restrict__ lnv_b)
{
    const int bh = blockIdx.x;
    const int chunk = blockIdx.y;
    const int b = bh >> 4, h = bh & 15;
    const int n0 = chunk * ROWS_PER_CHUNK;
    const long base = (long)b * (Ss * Ff) + (long)h * (512 * 1024);

    __shared__ __half ksh[16][72];
    __shared__ __half vsh[16][72];
    __shared__ float sks[64], skb[64], svs[64], svb[64];

    const int t = threadIdx.x;
    const int warp = t >> 5, lane = t & 31;

    if (t < 64) {
        sks[t] = lnk_s[h * 64 + t];
        skb[t] = lnk_b[h * 64 + t];
        svs[t] = lnv_s[h * 64 + t];
        svb[t] = lnv_b[h * 64 + t];
    }

    const int d0 = (warp >> 1) * 16;
    const int e0 = (warp & 1) * 32;

    const uint32_t aaddr = smem_u32(
        &ksh[(lane & 7) + ((lane >> 4) & 1) * 8][d0 + ((lane >> 3) & 1) * 8]);
    const uint32_t baddr0 = smem_u32(
        &vsh[(lane & 7) + ((lane >> 3) & 1) * 8][e0 + ((lane >> 4) & 1) * 8]);
    const uint32_t baddr1 = baddr0 + 16 * 2;

    float acc[4][4];
#pragma unroll
    for (int i = 0; i < 4; i++)
#pragma unroll
        for (int j = 0; j < 4; j++) acc[i][j] = 0.f;

    for (int r0 = 0; r0 < ROWS_PER_CHUNK; r0 += 16) {
        __syncthreads();
#pragma unroll
        for (int rr = 0; rr < 2; rr++) {
            int r = 2 * warp + rr;
            long off = base + (long)(n0 + r0 + r) * 64;

            __half2 kk = reinterpret_cast<const __half2*>(gKh + off)[lane];
            __half2 vv = reinterpret_cast<const __half2*>(gVh + off)[lane];
            float2 kf = __half22float2(kk);
            float2 vf = __half22float2(vv);

            float ksum = kf.x + kf.y, ksq = kf.x * kf.x + kf.y * kf.y;
            float vsum = vf.x + vf.y, vsq = vf.x * vf.x + vf.y * vf.y;
#pragma unroll
            for (int o = 16; o > 0; o >>= 1) {
                ksum += __shfl_xor_sync(0xffffffffu, ksum, o);
                ksq  += __shfl_xor_sync(0xffffffffu, ksq, o);
                vsum += __shfl_xor_sync(0xffffffffu, vsum, o);
                vsq  += __shfl_xor_sync(0xffffffffu, vsq, o);
            }
            float kmu = ksum * (1.f / 64.f);
            float kvar = ksq * (1.f / 64.f) - kmu * kmu;
            float krs = rsqrtf(kvar + 1e-6f);
            float vmu = vsum * (1.f / 64.f);
            float vvar = vsq * (1.f / 64.f) - vmu * vmu;
            float vrs = rsqrtf(vvar + 1e-6f);

            float nk0 = (kf.x - kmu) * krs * sks[2 * lane]     + skb[2 * lane];
            float nk1 = (kf.y - kmu) * krs * sks[2 * lane + 1] + skb[2 * lane + 1];
            float nv0 = (vf.x - vmu) * vrs * svs[2 * lane]     + svb[2 * lane];
            float nv1 = (vf.y - vmu) * vrs * svs[2 * lane + 1] + svb[2 * lane + 1];

            *reinterpret_cast<__half2*>(&ksh[r][2 * lane]) = __floats2half2_rn(nk0, nk1);
            *reinterpret_cast<__half2*>(&vsh[r][2 * lane]) = __floats2half2_rn(nv0, nv1);
        }
        __syncthreads();

        uint32_t a[4], bq0[4], bq1[4];
        ldm4t(a, aaddr);
        ldm4t(bq0, baddr0);
        ldm4t(bq1, baddr1);
        uint32_t bfr[4][2] = {{bq0[0], bq0[1]}, {bq0[2], bq0[3]},
                              {bq1[0], bq1[1]}, {bq1[2], bq1[3]}};
#pragma unroll
        for (int nf = 0; nf < 4; ++nf)
            mma16816(acc[nf], a, bfr[nf]);
    }

    float* p = gPpart + ((long)chunk * 64 + bh) * 4096;
    const int lrow = lane >> 2;
    const int lcol = (lane & 3) * 2;
#pragma unroll
    for (int nf = 0; nf < 4; ++nf) {
        int e = e0 + nf * 8 + lcol;
        *reinterpret_cast<float2*>(p + (d0 + lrow) * 64 + e) =
            make_float2(acc[nf][0], acc[nf][1]);
        *reinterpret_cast<float2*>(p + (d0 + lrow + 8) * 64 + e) =
            make_float2(acc[nf][2], acc[nf][3]);
    }
}

// reduce: fp32 p_attn output (required) + fp16 copy for out GEMM, float4 wide
__global__ void pattn_reduce_kernel(float* __restrict__ pout)
{
    int i4 = blockIdx.x * blockDim.x + threadIdx.x;    // 0..65535 (x4 elems)
    if (i4 >= 65536) return;
    const float4* part = reinterpret_cast<const float4*>(gPpart);
    float4 s = part[i4];
#pragma unroll
    for (int c = 1; c < NCHUNK; c++) {
        float4 v = part[(size_t)c * 65536 + i4];
        s.x += v.x; s.y += v.y; s.z += v.z; s.w += v.w;
    }
    s.x *= (1.f / 8192.f); s.y *= (1.f / 8192.f);
    s.z *= (1.f / 8192.f); s.w *= (1.f / 8192.f);
    reinterpret_cast<float4*>(pout)[i4] = s;
    __half2 h0 = __floats2half2_rn(s.x, s.y);
    __half2 h1 = __floats2half2_rn(s.z, s.w);
    reinterpret_cast<__half2*>(gPh)[2 * i4]     = h0;
    reinterpret_cast<__half2*>(gPh)[2 * i4 + 1] = h1;
}

// ---------------- out = Q @ P  (HMMA, fp16 inputs, fp32 out) -----------------
// Grid (64, 64): 64 n-tiles x 128 rows = 8192 rows per (b,h). 8 warps/block.
__global__ __launch_bounds__(256)
void out_kernel(float* __restrict__ out)
{
    const int bh = blockIdx.y;
    const int b = bh >> 4, h = bh & 15;
    const int n0 = blockIdx.x * 128;

    __shared__ __half psh[64][72];
    __shared__ __half qsh[128][72];

    const int t = threadIdx.x;
    const int warp = t >> 5, lane = t & 31;

    const __half* P = gPh + (size_t)bh * 4096;
    for (int i = t; i < 2048; i += 256) {            // P: 64x64, half2 units
        int d = i >> 5, e2 = (i & 31) * 2;
        *reinterpret_cast<__half2*>(&psh[d][e2]) =
            *reinterpret_cast<const __half2*>(P + d * 64 + e2);
    }
    const size_t base = (size_t)b * (Ss * Ff) + (size_t)h * 524288 + (size_t)n0 * 64;
    for (int i = t; i < 2048; i += 256) {            // Q: 128x64, 4-half units
        int n = i >> 4, d4 = (i & 15) * 4;
        *reinterpret_cast<uint2*>(&qsh[n][d4]) =
            *reinterpret_cast<const uint2*>(gQh + base + (size_t)n * 64 + d4);
    }
    __syncthreads();

    const int arow = (lane & 7) + ((lane >> 3) & 1) * 8;
    const int ao = ((lane >> 4) & 1) * 8;            // halves
    const int brow = (lane & 7) + ((lane >> 3) & 1) * 8;
    const int bo = ((lane >> 4) & 1) * 8;

    float acc[8][4];
#pragma unroll
    for (int i = 0; i < 8; i++)
#pragma unroll
        for (int q = 0; q < 4; q++) acc[i][q] = 0.f;

#pragma unroll
    for (int s = 0; s < 4; ++s) {                    // k = d, 4 steps of 16
        uint32_t a[4];
        ldm4(a, smem_u32(&qsh[warp * 16 + arow][s * 16 + ao]));
        uint32_t bfr[8][2];
#pragma unroll
        for (int g = 0; g < 4; ++g) {                // e groups of 16
            uint32_t r[4];
            ldm4t(r, smem_u32(&psh[s * 16 + brow][g * 16 + bo]));
            bfr[2 * g][0] = r[0]; bfr[2 * g][1] = r[1];
            bfr[2 * g + 1][0] = r[2]; bfr[2 * g + 1][1] = r[3];
        }
#pragma unroll
        for (int nf = 0; nf < 8; ++nf)
            mma16816(acc[nf], a, bfr[nf]);
    }

    const int lrow = lane >> 2;
    const int lcol = (lane & 3) * 2;
#pragma unroll
    for (int nf = 0; nf < 8; ++nf) {
        int e = nf * 8 + lcol;
        *reinterpret_cast<float2*>(out + base + (size_t)(warp * 16 + lrow) * 64 + e) =
            make_float2(acc[nf][0], acc[nf][1]);
        *reinterpret_cast<float2*>(out + base + (size_t)(warp * 16 + lrow + 8) * 64 + e) =
            make_float2(acc[nf][2], acc[nf][3]);
    }
}

// ---------------- launch ----------------------------------------------------
extern "C" void kernel_launch(void* const* d_in, const int* in_sizes, int n_in,
                              void* d_out, int out_size)
{
    (void)in_sizes; (void)n_in; (void)out_size;
    const float* query = (const float*)d_in[0];
    const float* key   = (const float*)d_in[1];
    const float* value = (const float*)d_in[2];
    const float* Wq    = (const float*)d_in[3];
    const float* Wk    = (const float*)d_in[4];
    const float* Wv    = (const float*)d_in[5];
    const float* lnk_s = (const float*)d_in[6];
    const float* lnk_b = (const float*)d_in[7];
    const float* lnv_s = (const float*)d_in[8];
    const float* lnv_b = (const float*)d_in[9];

    float* out = (float*)d_out;
    float* pout = out + QELEMS;

    // persistent side stream + events (created on first call, outside capture)
    static cudaStream_t s2 = nullptr;
    static cudaEvent_t evFork = nullptr, evJoin = nullptr;
    if (s2 == nullptr) {
        cudaStreamCreateWithFlags(&s2, cudaStreamNonBlocking);
        cudaEventCreateWithFlags(&evFork, cudaEventDisableTiming);
        cudaEventCreateWithFlags(&evJoin, cudaEventDisableTiming);
        cudaFuncSetAttribute(gemm_mma_kernel,
                             cudaFuncAttributeMaxDynamicSharedMemorySize,
                             3 * STAGE + 1024);
    }

    convert_A_kernel<<<dim3(16384, 3), 256>>>(query, key, value);
    convert_W_kernel<<<dim3(32, 32, 3), 256>>>(Wq, Wk, Wv);

    // K and V projections first (pattn chain depends on them)
    gemm_mma_kernel<<<dim3(8, 256, 2), 128, 3 * STAGE + 1024>>>(1);

    // fork: Q projection on side stream, pattn chain on main stream
    cudaEventRecord(evFork, 0);
    cudaStreamWaitEvent(s2, evFork, 0);
    gemm_mma_kernel<<<dim3(8, 256, 1), 128, 3 * STAGE + 1024, s2>>>(0);

    dim3 pgrid(64, NCHUNK);
    pattn_partial_kernel<<<pgrid, 256>>>(lnk_s, lnk_b, lnv_s, lnv_b);
    pattn_reduce_kernel<<<(65536 + 255) / 256, 256>>>(pout);

    // join: out needs gQh (s2) and gPh (main)
    cudaEventRecord(evJoin, s2);
    cudaStreamWaitEvent(0, evJoin, 0);

    out_kernel<<<dim3(64, 64), 256>>>(out);
}

// round 16
// speedup vs baseline: 1.0544x; 1.0309x over previous
#include <cuda_runtime.h>
#include <cuda_fp16.h>
#include <cstdint>

// ---------------- problem constants ----------------
static constexpr int Bb = 4, Ss = 8192, Ff = 1024, Hh = 16, Dd = 64;
static constexpr int Mm = Bb * Ss;              // 32768
static constexpr int Kk = 1024, Nn = 1024;
static constexpr long QELEMS = (long)Mm * Ff;   // 33554432
static constexpr int NCHUNK = 32;
static constexpr int ROWS_PER_CHUNK = 8192 / NCHUNK;  // 256

// ---------------- scratch (device globals) ----------------
__device__ __half gQh[33554432];                // Q projection, fp16
__device__ __half gKh[33554432];                // K projection, fp16
__device__ __half gVh[33554432];                // V projection, fp16
__device__ float gPpart[(long)NCHUNK * 64 * 4096];
__device__ __half gPh[64 * 4096];               // fp16 copy of p_attn for out HMMA
__device__ __half gAh[3L * 33554432];
__device__ __half gWt[3L * 1048576];            // W^T: [n][k], k contiguous, fp16

// ---------------- helpers ----------------
__device__ __forceinline__ uint32_t smem_u32(const void* p) {
    uint32_t a;
    asm("{ .reg .u64 t; cvta.to.shared.u64 t, %1; cvt.u32.u64 %0, t; }" : "=r"(a) : "l"(p));
    return a;
}
// Swizzle<3,4,3> for 128B rows: XOR 16B-chunk bits [4:6] with row bits [7:9]
__device__ __forceinline__ uint32_t SZ128(uint32_t a) { return a ^ ((a >> 3) & 0x70u); }

__device__ __forceinline__ void cp16(uint32_t dst, const void* src) {
    asm volatile("cp.async.cg.shared.global [%0], [%1], 16;\n" :: "r"(dst), "l"(src));
}
__device__ __forceinline__ void cp_commit() { asm volatile("cp.async.commit_group;\n"); }
template<int N> __device__ __forceinline__ void cp_wait() {
    asm volatile("cp.async.wait_group %0;\n" :: "n"(N));
}
__device__ __forceinline__ void ldm4(uint32_t* r, uint32_t addr) {
    asm volatile("ldmatrix.sync.aligned.m8n8.x4.shared.b16 {%0,%1,%2,%3}, [%4];"
                 : "=r"(r[0]), "=r"(r[1]), "=r"(r[2]), "=r"(r[3]) : "r"(addr));
}
__device__ __forceinline__ void ldm4t(uint32_t* r, uint32_t addr) {
    asm volatile("ldmatrix.sync.aligned.m8n8.x4.trans.shared.b16 {%0,%1,%2,%3}, [%4];"
                 : "=r"(r[0]), "=r"(r[1]), "=r"(r[2]), "=r"(r[3]) : "r"(addr));
}
__device__ __forceinline__ void mma16816(float* d, const uint32_t* a, const uint32_t* b) {
    asm volatile(
        "mma.sync.aligned.m16n8k16.row.col.f32.f16.f16.f32 "
        "{%0,%1,%2,%3}, {%4,%5,%6,%7}, {%8,%9}, {%0,%1,%2,%3};"
        : "+f"(d[0]), "+f"(d[1]), "+f"(d[2]), "+f"(d[3])
        : "r"(a[0]), "r"(a[1]), "r"(a[2]), "r"(a[3]), "r"(b[0]), "r"(b[1]));
}

// ---------------- conversion prepasses ----------------
__global__ __launch_bounds__(256)
void convert_A_kernel(const float* __restrict__ src, int which)
{
    __half* hi = gAh + (size_t)which * 33554432;

    size_t i8 = (size_t)blockIdx.x * blockDim.x + threadIdx.x;   // 0..4194303
    float4 x0 = reinterpret_cast<const float4*>(src)[2 * i8];
    float4 x1 = reinterpret_cast<const float4*>(src)[2 * i8 + 1];

    __half2 a0 = __halves2half2(__float2half_rn(x0.x), __float2half_rn(x0.y));
    __half2 a1 = __halves2half2(__float2half_rn(x0.z), __float2half_rn(x0.w));
    __half2 a2 = __halves2half2(__float2half_rn(x1.x), __float2half_rn(x1.y));
    __half2 a3 = __halves2half2(__float2half_rn(x1.z), __float2half_rn(x1.w));
    uint4 u;
    u.x = *reinterpret_cast<unsigned*>(&a0);
    u.y = *reinterpret_cast<unsigned*>(&a1);
    u.z = *reinterpret_cast<unsigned*>(&a2);
    u.w = *reinterpret_cast<unsigned*>(&a3);
    reinterpret_cast<uint4*>(hi)[i8] = u;
}

__global__ __launch_bounds__(256)
void convert_W_kernel(const float* __restrict__ wq, const float* __restrict__ wk,
                      const float* __restrict__ wv)
{
    const int which = blockIdx.z;
    const float* W = (which == 0) ? wq : (which == 1) ? wk : wv;
    __half* hi = gWt + (size_t)which * 1048576;

    __shared__ float tile[32][33];
    const int bx = blockIdx.x * 32;   // n block
    const int by = blockIdx.y * 32;   // k block
    const int tx = threadIdx.x & 31;
    const int ty = threadIdx.x >> 5;  // 0..7

#pragma unroll
    for (int i = 0; i < 32; i += 8)
        tile[ty + i][tx] = W[(size_t)(by + ty + i) * 1024 + bx + tx];
    __syncthreads();
#pragma unroll
    for (int i = 0; i < 32; i += 8) {
        float x = tile[tx][ty + i];                 // = W[by+tx][bx+ty+i]
        size_t o = (size_t)(bx + ty + i) * 1024 + by + tx;   // Wt[n][k]
        hi[o] = __float2half_rn(x);
    }
}

// ---------------- HMMA GEMM: C[M,N] = A @ W  (fp16, 3-stage) -----------------
// Tile 128x128xK64, 4 warps (2m x 2n), 64x64 warp tiles, occ 2.
static constexpr int STAGE = 32768;
static constexpr int NCH = 16;        // 1024 / 64

__global__ __launch_bounds__(128, 2)
void gemm_mma_kernel(int which)
{
    extern __shared__ char smem[];
    const int n0 = blockIdx.x * 128;
    const int m0 = blockIdx.y * 128;
    const int tid = threadIdx.x;
    const int wid = tid >> 5, lane = tid & 31;

    const uint32_t tiles = (smem_u32(smem) + 1023) & ~1023u;

    const __half* Ah = gAh + (size_t)which * 33554432;
    const __half* Bp = gWt + (size_t)which * 1048576;

    const int mbase_w = (wid & 1) * 64;
    const int nbase_w = (wid >> 1) * 64;

    float acc[4][8][4];
#pragma unroll
    for (int i = 0; i < 4; i++)
#pragma unroll
        for (int j = 0; j < 8; j++)
#pragma unroll
            for (int q = 0; q < 4; q++) acc[i][j][q] = 0.f;

    auto load_chunk = [&](int buf, int c) {
        const uint32_t base = tiles + buf * STAGE;
        const int k0 = c * 64;
#pragma unroll
        for (int i = tid; i < 1024; i += 128) {         // A: 128 rows x 8 chunks
            int r = i >> 3, c8 = i & 7;
            size_t gb = ((size_t)(m0 + r) * 1024 + k0 + c8 * 8) * 2;
            uint32_t d = SZ128((uint32_t)(r * 128 + c8 * 16));
            cp16(base + d, (const char*)Ah + gb);
        }
#pragma unroll
        for (int i = tid; i < 1024; i += 128) {         // B: 128 rows x 8 chunks
            int r = i >> 3, c8 = i & 7;
            size_t gb = ((size_t)(n0 + r) * 1024 + k0 + c8 * 8) * 2;
            uint32_t d = SZ128((uint32_t)(r * 128 + c8 * 16));
            cp16(base + 16384 + d, (const char*)Bp + gb);
        }
        cp_commit();
    };

    load_chunk(0, 0);
    load_chunk(1, 1);

    const int arow = (lane & 7) + ((lane >> 3) & 1) * 8;
    const int aoff = ((lane >> 4) & 1) * 16;
    const int brow = (lane & 7) + ((lane >> 4) & 1) * 8;
    const int boff = ((lane >> 3) & 1) * 16;

    int buf = 0;
    for (int c = 0; c < NCH; ++c) {
        if (c < NCH - 1) cp_wait<1>(); else cp_wait<0>();
        __syncthreads();
        if (c + 2 < NCH) load_chunk((buf + 2) % 3, c + 2);

        const uint32_t ab = tiles + buf * STAGE;
        const uint32_t bb = ab + 16384;

#pragma unroll
        for (int s = 0; s < 4; ++s) {
            uint32_t ah[4][4], bh2[8][2];
#pragma unroll
            for (int bg = 0; bg < 4; ++bg) {            // 4 x 16-col B groups = 64 n
                uint32_t u = SZ128((uint32_t)((nbase_w + bg * 16 + brow) * 128 + s * 32 + boff));
                uint32_t r[4];
                ldm4(r, bb + u);
                bh2[2 * bg][0] = r[0]; bh2[2 * bg][1] = r[1];
                bh2[2 * bg + 1][0] = r[2]; bh2[2 * bg + 1][1] = r[3];
            }
#pragma unroll
            for (int mf = 0; mf < 4; ++mf) {
                uint32_t u = SZ128((uint32_t)((mbase_w + mf * 16 + arow) * 128 + s * 32 + aoff));
                ldm4(ah[mf], ab + u);
            }
#pragma unroll
            for (int mf = 0; mf < 4; ++mf)
#pragma unroll
                for (int nf = 0; nf < 8; ++nf)
                    mma16816(acc[mf][nf], ah[mf], bh2[nf]);
        }
        buf = (buf + 1) % 3;
    }

    // epilogue: all projections stored fp16
    __half* Ch = (which == 0) ? gQh : (which == 1) ? gKh : gVh;
    const int lrow = lane >> 2;
    const int lcol = (lane & 3) * 2;
#pragma unroll
    for (int mf = 0; mf < 4; ++mf)
#pragma unroll
        for (int nf = 0; nf < 8; ++nf) {
            int rm = m0 + mbase_w + mf * 16 + lrow;
            int cn = n0 + nbase_w + nf * 8 + lcol;
            *reinterpret_cast<__half2*>(Ch + (size_t)rm * 1024 + cn) =
                __floats2half2_rn(acc[mf][nf][0], acc[mf][nf][1]);
            *reinterpret_cast<__half2*>(Ch + (size_t)(rm + 8) * 1024 + cn) =
                __floats2half2_rn(acc[mf][nf][2], acc[mf][nf][3]);
        }
}

// ---------------- p_attn partials: LN(K)^T LN(V), HMMA consumer --------------
// 16 rows staged per iteration (2 rows/warp) — R12-validated schedule.
__global__ __launch_bounds__(256)
void pattn_partial_kernel(const float* __restrict__ lnk_s, const float* __restrict__ lnk_b,
                          const float* __restrict__ lnv_s, const float* __restrict__ lnv_b)
{
    const int bh = blockIdx.x;
    const int chunk = blockIdx.y;
    const int b = bh >> 4, h = bh & 15;
    const int n0 = chunk * ROWS_PER_CHUNK;
    const long base = (long)b * (Ss * Ff) + (long)h * (512 * 1024);

    __shared__ __half ksh[16][72];
    __shared__ __half vsh[16][72];
    __shared__ float sks[64], skb[64], svs[64], svb[64];

    const int t = threadIdx.x;
    const int warp = t >> 5, lane = t & 31;

    if (t < 64) {
        sks[t] = lnk_s[h * 64 + t];
        skb[t] = lnk_b[h * 64 + t];
        svs[t] = lnv_s[h * 64 + t];
        svb[t] = lnv_b[h * 64 + t];
    }

    const int d0 = (warp >> 1) * 16;
    const int e0 = (warp & 1) * 32;

    const uint32_t aaddr = smem_u32(
        &ksh[(lane & 7) + ((lane >> 4) & 1) * 8][d0 + ((lane >> 3) & 1) * 8]);
    const uint32_t baddr0 = smem_u32(
        &vsh[(lane & 7) + ((lane >> 3) & 1) * 8][e0 + ((lane >> 4) & 1) * 8]);
    const uint32_t baddr1 = baddr0 + 16 * 2;

    float acc[4][4];
#pragma unroll
    for (int i = 0; i < 4; i++)
#pragma unroll
        for (int j = 0; j < 4; j++) acc[i][j] = 0.f;

    for (int r0 = 0; r0 < ROWS_PER_CHUNK; r0 += 16) {
        __syncthreads();
#pragma unroll
        for (int rr = 0; rr < 2; rr++) {
            int r = 2 * warp + rr;
            long off = base + (long)(n0 + r0 + r) * 64;

            __half2 kk = reinterpret_cast<const __half2*>(gKh + off)[lane];
            __half2 vv = reinterpret_cast<const __half2*>(gVh + off)[lane];
            float2 kf = __half22float2(kk);
            float2 vf = __half22float2(vv);

            float ksum = kf.x + kf.y, ksq = kf.x * kf.x + kf.y * kf.y;
            float vsum = vf.x + vf.y, vsq = vf.x * vf.x + vf.y * vf.y;
#pragma unroll
            for (int o = 16; o > 0; o >>= 1) {
                ksum += __shfl_xor_sync(0xffffffffu, ksum, o);
                ksq  += __shfl_xor_sync(0xffffffffu, ksq, o);
                vsum += __shfl_xor_sync(0xffffffffu, vsum, o);
                vsq  += __shfl_xor_sync(0xffffffffu, vsq, o);
            }
            float kmu = ksum * (1.f / 64.f);
            float kvar = ksq * (1.f / 64.f) - kmu * kmu;
            float krs = rsqrtf(kvar + 1e-6f);
            float vmu = vsum * (1.f / 64.f);
            float vvar = vsq * (1.f / 64.f) - vmu * vmu;
            float vrs = rsqrtf(vvar + 1e-6f);

            float nk0 = (kf.x - kmu) * krs * sks[2 * lane]     + skb[2 * lane];
            float nk1 = (kf.y - kmu) * krs * sks[2 * lane + 1] + skb[2 * lane + 1];
            float nv0 = (vf.x - vmu) * vrs * svs[2 * lane]     + svb[2 * lane];
            float nv1 = (vf.y - vmu) * vrs * svs[2 * lane + 1] + svb[2 * lane + 1];

            *reinterpret_cast<__half2*>(&ksh[r][2 * lane]) = __floats2half2_rn(nk0, nk1);
            *reinterpret_cast<__half2*>(&vsh[r][2 * lane]) = __floats2half2_rn(nv0, nv1);
        }
        __syncthreads();

        uint32_t a[4], bq0[4], bq1[4];
        ldm4t(a, aaddr);
        ldm4t(bq0, baddr0);
        ldm4t(bq1, baddr1);
        uint32_t bfr[4][2] = {{bq0[0], bq0[1]}, {bq0[2], bq0[3]},
                              {bq1[0], bq1[1]}, {bq1[2], bq1[3]}};
#pragma unroll
        for (int nf = 0; nf < 4; ++nf)
            mma16816(acc[nf], a, bfr[nf]);
    }

    float* p = gPpart + ((long)chunk * 64 + bh) * 4096;
    const int lrow = lane >> 2;
    const int lcol = (lane & 3) * 2;
#pragma unroll
    for (int nf = 0; nf < 4; ++nf) {
        int e = e0 + nf * 8 + lcol;
        *reinterpret_cast<float2*>(p + (d0 + lrow) * 64 + e) =
            make_float2(acc[nf][0], acc[nf][1]);
        *reinterpret_cast<float2*>(p + (d0 + lrow + 8) * 64 + e) =
            make_float2(acc[nf][2], acc[nf][3]);
    }
}

// reduce: fp32 p_attn output (required) + fp16 copy for out GEMM, float4 wide
__global__ void pattn_reduce_kernel(float* __restrict__ pout)
{
    int i4 = blockIdx.x * blockDim.x + threadIdx.x;    // 0..65535 (x4 elems)
    if (i4 >= 65536) return;
    const float4* part = reinterpret_cast<const float4*>(gPpart);
    float4 s = part[i4];
#pragma unroll
    for (int c = 1; c < NCHUNK; c++) {
        float4 v = part[(size_t)c * 65536 + i4];
        s.x += v.x; s.y += v.y; s.z += v.z; s.w += v.w;
    }
    s.x *= (1.f / 8192.f); s.y *= (1.f / 8192.f);
    s.z *= (1.f / 8192.f); s.w *= (1.f / 8192.f);
    reinterpret_cast<float4*>(pout)[i4] = s;
    __half2 h0 = __floats2half2_rn(s.x, s.y);
    __half2 h1 = __floats2half2_rn(s.z, s.w);
    reinterpret_cast<__half2*>(gPh)[2 * i4]     = h0;
    reinterpret_cast<__half2*>(gPh)[2 * i4 + 1] = h1;
}

// ---------------- out = Q @ P  (HMMA, fp16 inputs, fp32 out) -----------------
// Grid (64, 64): 64 n-tiles x 128 rows = 8192 rows per (b,h). 8 warps/block.
__global__ __launch_bounds__(256)
void out_kernel(float* __restrict__ out)
{
    const int bh = blockIdx.y;
    const int b = bh >> 4, h = bh & 15;
    const int n0 = blockIdx.x * 128;

    __shared__ __half psh[64][72];
    __shared__ __half qsh[128][72];

    const int t = threadIdx.x;
    const int warp = t >> 5, lane = t & 31;

    const __half* P = gPh + (size_t)bh * 4096;
    for (int i = t; i < 2048; i += 256) {            // P: 64x64, half2 units
        int d = i >> 5, e2 = (i & 31) * 2;
        *reinterpret_cast<__half2*>(&psh[d][e2]) =
            *reinterpret_cast<const __half2*>(P + d * 64 + e2);
    }
    const size_t base = (size_t)b * (Ss * Ff) + (size_t)h * 524288 + (size_t)n0 * 64;
    for (int i = t; i < 2048; i += 256) {            // Q: 128x64, 4-half units
        int n = i >> 4, d4 = (i & 15) * 4;
        *reinterpret_cast<uint2*>(&qsh[n][d4]) =
            *reinterpret_cast<const uint2*>(gQh + base + (size_t)n * 64 + d4);
    }
    __syncthreads();

    const int arow = (lane & 7) + ((lane >> 3) & 1) * 8;
    const int ao = ((lane >> 4) & 1) * 8;            // halves
    const int brow = (lane & 7) + ((lane >> 3) & 1) * 8;
    const int bo = ((lane >> 4) & 1) * 8;

    float acc[8][4];
#pragma unroll
    for (int i = 0; i < 8; i++)
#pragma unroll
        for (int q = 0; q < 4; q++) acc[i][q] = 0.f;

#pragma unroll
    for (int s = 0; s < 4; ++s) {                    // k = d, 4 steps of 16
        uint32_t a[4];
        ldm4(a, smem_u32(&qsh[warp * 16 + arow][s * 16 + ao]));
        uint32_t bfr[8][2];
#pragma unroll
        for (int g = 0; g < 4; ++g) {                // e groups of 16
            uint32_t r[4];
            ldm4t(r, smem_u32(&psh[s * 16 + brow][g * 16 + bo]));
            bfr[2 * g][0] = r[0]; bfr[2 * g][1] = r[1];
            bfr[2 * g + 1][0] = r[2]; bfr[2 * g + 1][1] = r[3];
        }
#pragma unroll
        for (int nf = 0; nf < 8; ++nf)
            mma16816(acc[nf], a, bfr[nf]);
    }

    const int lrow = lane >> 2;
    const int lcol = (lane & 3) * 2;
#pragma unroll
    for (int nf = 0; nf < 8; ++nf) {
        int e = nf * 8 + lcol;
        *reinterpret_cast<float2*>(out + base + (size_t)(warp * 16 + lrow) * 64 + e) =
            make_float2(acc[nf][0], acc[nf][1]);
        *reinterpret_cast<float2*>(out + base + (size_t)(warp * 16 + lrow + 8) * 64 + e) =
            make_float2(acc[nf][2], acc[nf][3]);
    }
}

// ---------------- launch ----------------------------------------------------
extern "C" void kernel_launch(void* const* d_in, const int* in_sizes, int n_in,
                              void* d_out, int out_size)
{
    (void)in_sizes; (void)n_in; (void)out_size;
    const float* query = (const float*)d_in[0];
    const float* key   = (const float*)d_in[1];
    const float* value = (const float*)d_in[2];
    const float* Wq    = (const float*)d_in[3];
    const float* Wk    = (const float*)d_in[4];
    const float* Wv    = (const float*)d_in[5];
    const float* lnk_s = (const float*)d_in[6];
    const float* lnk_b = (const float*)d_in[7];
    const float* lnv_s = (const float*)d_in[8];
    const float* lnv_b = (const float*)d_in[9];

    float* out = (float*)d_out;
    float* pout = out + QELEMS;

    // persistent side stream + events (created on first call, outside capture)
    static cudaStream_t s2 = nullptr;
    static cudaEvent_t evF = nullptr, evV = nullptr, evJ = nullptr;
    if (s2 == nullptr) {
        cudaStreamCreateWithFlags(&s2, cudaStreamNonBlocking);
        cudaEventCreateWithFlags(&evF, cudaEventDisableTiming);
        cudaEventCreateWithFlags(&evV, cudaEventDisableTiming);
        cudaEventCreateWithFlags(&evJ, cudaEventDisableTiming);
        cudaFuncSetAttribute(gemm_mma_kernel,
                             cudaFuncAttributeMaxDynamicSharedMemorySize,
                             3 * STAGE + 1024);
    }

    // main: W converts + K convert (GEMM(K)'s prerequisites)
    convert_W_kernel<<<dim3(32, 32, 3), 256>>>(Wq, Wk, Wv);
    convert_A_kernel<<<16384, 256>>>(key, 1);

    // fork: V and Q converts + GEMM(Q) on side stream — they hide under
    // main's GEMM(K)/GEMM(V) (DRAM 7% busy, 12% warp occ during GEMMs)
    cudaEventRecord(evF, 0);
    cudaStreamWaitEvent(s2, evF, 0);
    convert_A_kernel<<<16384, 256, 0, s2>>>(value, 2);
    cudaEventRecord(evV, s2);
    convert_A_kernel<<<16384, 256, 0, s2>>>(query, 0);
    gemm_mma_kernel<<<dim3(8, 256), 128, 3 * STAGE + 1024, s2>>>(0);
    cudaEventRecord(evJ, s2);

    // main: K projection, then V (after V's convert), then pattn chain
    gemm_mma_kernel<<<dim3(8, 256), 128, 3 * STAGE + 1024>>>(1);
    cudaStreamWaitEvent(0, evV, 0);
    gemm_mma_kernel<<<dim3(8, 256), 128, 3 * STAGE + 1024>>>(2);

    dim3 pgrid(64, NCHUNK);
    pattn_partial_kernel<<<pgrid, 256>>>(lnk_s, lnk_b, lnv_s, lnv_b);
    pattn_reduce_kernel<<<(65536 + 255) / 256, 256>>>(pout);

    // join: out needs gQh (s2) and gPh (main)
    cudaStreamWaitEvent(0, evJ, 0);
    out_kernel<<<dim3(64, 64), 256>>>(out);
}